// round 6
// baseline (speedup 1.0000x reference)
#include <cuda_runtime.h>
#include <cuda_bf16.h>
#include <cstdint>

#define NROWS 1048576
#define DIM   128
#define NSEG  4096

// Scratch (__device__ globals per allocation-free rule)
__device__ float g_xs[NSEG * DIM];                          // segment sums (2 MB)
__device__ float g_xm[NSEG * DIM];                          // xs @ Lambda^T (2 MB)
__device__ __align__(16) __nv_bfloat16 g_Gb[DIM * DIM];     // Gamma bf16 [n][k]

__device__ __forceinline__ uint32_t smem_u32(const void* p) {
    uint32_t a;
    asm("{ .reg .u64 t; cvta.to.shared.u64 t, %1; cvt.u32.u64 %0, t; }" : "=r"(a) : "l"(p));
    return a;
}
__device__ __forceinline__ uint32_t pack_bf16x2(float lo, float hi) {
    uint32_t r;
    asm("cvt.rn.bf16x2.f32 %0, %1, %2;" : "=r"(r) : "f"(hi), "f"(lo));
    return r;
}

// ---------------------------------------------------------------------------
// Kernel 0: zero g_xs, convert Gamma_W -> bf16 (plain [n][k] layout)
// ---------------------------------------------------------------------------
__global__ void k0_init(const float* __restrict__ GW) {
    int idx = blockIdx.x * blockDim.x + threadIdx.x;
    if (idx < NSEG * DIM) g_xs[idx] = 0.0f;
    if (idx < DIM * DIM)  g_Gb[idx] = __float2bfloat16(GW[idx]);
}

// ---------------------------------------------------------------------------
// Kernel 1: segment sum (sorted ids, register run-length, boundary atomics)
// ---------------------------------------------------------------------------
__global__ __launch_bounds__(256) void k1_segsum(const float* __restrict__ x,
                                                 const int* __restrict__ seg) {
    int t = threadIdx.x;
    int stream = t >> 5;
    int c = (t & 31) * 4;
    int base = blockIdx.x * 1024 + stream;

    float4 acc = make_float4(0.f, 0.f, 0.f, 0.f);
    int cur = seg[base];

    #pragma unroll 8
    for (int i = 0; i < 128; i++) {
        int r = base + i * 8;
        int s = seg[r];
        float4 v = *(const float4*)(x + (size_t)r * DIM + c);
        if (s != cur) {
            float* d = g_xs + (size_t)cur * DIM + c;
            atomicAdd(d + 0, acc.x); atomicAdd(d + 1, acc.y);
            atomicAdd(d + 2, acc.z); atomicAdd(d + 3, acc.w);
            acc = make_float4(0.f, 0.f, 0.f, 0.f);
            cur = s;
        }
        acc.x += v.x; acc.y += v.y; acc.z += v.z; acc.w += v.w;
    }
    float* d = g_xs + (size_t)cur * DIM + c;
    atomicAdd(d + 0, acc.x); atomicAdd(d + 1, acc.y);
    atomicAdd(d + 2, acc.z); atomicAdd(d + 3, acc.w);
}

// ---------------------------------------------------------------------------
// Kernel 2: g_xm = g_xs @ Lambda_W^T (fp32 exact)
// ---------------------------------------------------------------------------
__global__ __launch_bounds__(128) void k2_xm(const float* __restrict__ LW) {
    extern __shared__ float sm2[];
    float* Lt  = sm2;                 // [128][129]
    float* xss = sm2 + 128 * 129;     // [16][128]
    int t = threadIdx.x;
    int R0 = blockIdx.x * 16;

    for (int i = 0; i < 128; i++) {
        int e = i * 128 + t;
        int j = e >> 7, k = e & 127;
        Lt[k * 129 + j] = LW[e];
    }
    for (int i = 0; i < 16; i++) {
        int e = i * 128 + t;
        int r = e >> 7, k = e & 127;
        xss[r * 128 + k] = g_xs[(size_t)(R0 + r) * DIM + k];
    }
    __syncthreads();

    float acc[16];
    #pragma unroll
    for (int r = 0; r < 16; r++) acc[r] = 0.f;
    for (int k = 0; k < 128; k++) {
        float lv = Lt[k * 129 + t];
        #pragma unroll
        for (int r = 0; r < 16; r++) acc[r] += xss[r * 128 + k] * lv;
    }
    #pragma unroll
    for (int r = 0; r < 16; r++)
        g_xm[(size_t)(R0 + r) * DIM + t] = acc[r];
}

// ---------------------------------------------------------------------------
// Kernel 3: out = x @ Gamma^T (bf16 HMMA) + bias - xm[seg]
// 128 threads = 4 warps; block tile 128x128; warp tile 64x64 quadrant.
// Fragment traffic/block: LDSM (64+64)*128*2*4 = 128 KB (vs 288 KB in the
// 8x(16x128) layout). acc = 128 regs/lane; __launch_bounds__(128,2) -> 256 cap.
// ---------------------------------------------------------------------------
#define ASTRIDE 136
#define K3_SMEM (2 * 128 * ASTRIDE * 2)   // 69632 bytes

__global__ __launch_bounds__(128, 2) void k3_main(const float* __restrict__ x,
                                                  const int* __restrict__ seg,
                                                  const float* __restrict__ bias,
                                                  float* __restrict__ out) {
    extern __shared__ __nv_bfloat16 sm3[];
    __nv_bfloat16* As = sm3;                       // [128][136]
    __nv_bfloat16* Bs = sm3 + 128 * ASTRIDE;       // [128][136]  Bs[n][k]

    int tid  = threadIdx.x;
    int warp = tid >> 5;
    int lane = tid & 31;
    int r0 = blockIdx.x * 128;
    int m0 = (warp & 1) * 64;
    int n0 = (warp >> 1) * 64;
    uint32_t sbB = smem_u32(Bs);

    // Stage B via cp.async (32 KB, padded rows)
    #pragma unroll
    for (int i = 0; i < 16; i++) {
        int e = i * 128 + tid;
        int row = e >> 4, c = e & 15;
        asm volatile("cp.async.cg.shared.global [%0], [%1], 16;"
                     :: "r"(sbB + (row * ASTRIDE + c * 8) * 2),
                        "l"((const char*)(g_Gb + row * 128 + c * 8)) : "memory");
    }
    asm volatile("cp.async.commit_group;" ::: "memory");

    // Stage A: LDG fp32 -> bf16 -> STS.128
    uint32_t sbA = smem_u32(As);
    #pragma unroll
    for (int i = 0; i < 16; i++) {
        int e = i * 128 + tid;
        int row = e >> 4, g2 = e & 15;
        const float4* src = (const float4*)(x + (size_t)(r0 + row) * DIM + g2 * 8);
        float4 v0 = src[0], v1 = src[1];
        uint32_t p0 = pack_bf16x2(v0.x, v0.y);
        uint32_t p1 = pack_bf16x2(v0.z, v0.w);
        uint32_t p2 = pack_bf16x2(v1.x, v1.y);
        uint32_t p3 = pack_bf16x2(v1.z, v1.w);
        asm volatile("st.shared.v4.b32 [%0], {%1,%2,%3,%4};"
                     :: "r"(sbA + (row * ASTRIDE + g2 * 8) * 2),
                        "r"(p0), "r"(p1), "r"(p2), "r"(p3) : "memory");
    }

    // Prefetch epilogue seg ids (8 rows/lane)
    int g  = lane >> 2;
    int t4 = lane & 3;
    int sa[4], sb2[4];
    #pragma unroll
    for (int mt = 0; mt < 4; mt++) {
        int ra = r0 + m0 + mt * 16 + g;
        sa[mt]  = seg[ra];
        sb2[mt] = seg[ra + 8];
    }

    asm volatile("cp.async.wait_group 0;" ::: "memory");
    __syncthreads();

    // Fragment base addresses
    const __nv_bfloat16* ap[4];
    #pragma unroll
    for (int mt = 0; mt < 4; mt++)
        ap[mt] = As + (m0 + mt * 16 + (lane & 15)) * ASTRIDE + ((lane >> 4) << 3);
    const __nv_bfloat16* bp =
        Bs + (n0 + (lane & 7) + ((lane >> 4) << 3)) * ASTRIDE + (((lane >> 3) & 1) << 3);

    float acc[4][8][4];
    #pragma unroll
    for (int mt = 0; mt < 4; mt++)
        #pragma unroll
        for (int nt = 0; nt < 8; nt++)
            #pragma unroll
            for (int q = 0; q < 4; q++) acc[mt][nt][q] = 0.f;

    #pragma unroll
    for (int ks = 0; ks < 8; ks++) {
        uint32_t a[4][4], b[4][4];
        #pragma unroll
        for (int mt = 0; mt < 4; mt++) {
            uint32_t addr = (uint32_t)__cvta_generic_to_shared(ap[mt] + ks * 16);
            asm volatile(
                "ldmatrix.sync.aligned.m8n8.x4.shared.b16 {%0,%1,%2,%3}, [%4];"
                : "=r"(a[mt][0]), "=r"(a[mt][1]), "=r"(a[mt][2]), "=r"(a[mt][3])
                : "r"(addr));
        }
        #pragma unroll
        for (int np = 0; np < 4; np++) {
            uint32_t addr = (uint32_t)__cvta_generic_to_shared(
                bp + np * 16 * ASTRIDE + ks * 16);
            asm volatile(
                "ldmatrix.sync.aligned.m8n8.x4.shared.b16 {%0,%1,%2,%3}, [%4];"
                : "=r"(b[np][0]), "=r"(b[np][1]), "=r"(b[np][2]), "=r"(b[np][3])
                : "r"(addr));
        }
        #pragma unroll
        for (int mt = 0; mt < 4; mt++)
            #pragma unroll
            for (int np = 0; np < 4; np++) {
                asm volatile(
                    "mma.sync.aligned.m16n8k16.row.col.f32.bf16.bf16.f32 "
                    "{%0,%1,%2,%3}, {%4,%5,%6,%7}, {%8,%9}, {%0,%1,%2,%3};\n"
                    : "+f"(acc[mt][2 * np][0]), "+f"(acc[mt][2 * np][1]),
                      "+f"(acc[mt][2 * np][2]), "+f"(acc[mt][2 * np][3])
                    : "r"(a[mt][0]), "r"(a[mt][1]), "r"(a[mt][2]), "r"(a[mt][3]),
                      "r"(b[np][0]), "r"(b[np][1]));
                asm volatile(
                    "mma.sync.aligned.m16n8k16.row.col.f32.bf16.bf16.f32 "
                    "{%0,%1,%2,%3}, {%4,%5,%6,%7}, {%8,%9}, {%0,%1,%2,%3};\n"
                    : "+f"(acc[mt][2 * np + 1][0]), "+f"(acc[mt][2 * np + 1][1]),
                      "+f"(acc[mt][2 * np + 1][2]), "+f"(acc[mt][2 * np + 1][3])
                    : "r"(a[mt][0]), "r"(a[mt][1]), "r"(a[mt][2]), "r"(a[mt][3]),
                      "r"(b[np][2]), "r"(b[np][3]));
            }
    }

    // Epilogue: + bias - xm[seg]; sector-aligned float2 stores
    float2 bias_r[8];
    #pragma unroll
    for (int nt = 0; nt < 8; nt++)
        bias_r[nt] = *(const float2*)(bias + n0 + nt * 8 + 2 * t4);

    #pragma unroll
    for (int mt = 0; mt < 4; mt++) {
        const float* xa = g_xm + (size_t)sa[mt] * DIM;
        const float* xb = g_xm + (size_t)sb2[mt] * DIM;
        int ra = r0 + m0 + mt * 16 + g;
        int rb = ra + 8;
        #pragma unroll
        for (int nt = 0; nt < 8; nt++) {
            int j = n0 + nt * 8 + 2 * t4;
            float2 ma = *(const float2*)(xa + j);
            float2 mb = *(const float2*)(xb + j);
            float2 oa, ob;
            oa.x = acc[mt][nt][0] + bias_r[nt].x - ma.x;
            oa.y = acc[mt][nt][1] + bias_r[nt].y - ma.y;
            ob.x = acc[mt][nt][2] + bias_r[nt].x - mb.x;
            ob.y = acc[mt][nt][3] + bias_r[nt].y - mb.y;
            *(float2*)(out + (size_t)ra * DIM + j) = oa;
            *(float2*)(out + (size_t)rb * DIM + j) = ob;
        }
    }
}

// ---------------------------------------------------------------------------
extern "C" void kernel_launch(void* const* d_in, const int* in_sizes, int n_in,
                              void* d_out, int out_size) {
    const float* x   = (const float*)d_in[0];
    const int*   seg = (const int*)d_in[1];
    const float* GW = nullptr;
    const float* Gb = nullptr;
    const float* LW = nullptr;
    for (int i = 2; i < n_in; i++) {
        int s = in_sizes[i];
        if (s == DIM * DIM) { if (!GW) GW = (const float*)d_in[i]; else LW = (const float*)d_in[i]; }
        else if (s == DIM) { Gb = (const float*)d_in[i]; }
    }
    float* out = (float*)d_out;

    cudaFuncSetAttribute(k2_xm,   cudaFuncAttributeMaxDynamicSharedMemorySize, 74240);
    cudaFuncSetAttribute(k3_main, cudaFuncAttributeMaxDynamicSharedMemorySize, K3_SMEM);

    k0_init<<<2048, 256>>>(GW);
    k1_segsum<<<NROWS / 1024, 256>>>(x, seg);
    k2_xm<<<NSEG / 16, 128, 74240>>>(LW);
    k3_main<<<NROWS / 128, 128, K3_SMEM>>>(x, seg, Gb, out);
}

// round 7
// speedup vs baseline: 1.0585x; 1.0585x over previous
#include <cuda_runtime.h>
#include <cuda_bf16.h>
#include <cstdint>

#define NROWS 1048576
#define DIM   128
#define NSEG  4096

// Scratch (__device__ globals per allocation-free rule)
__device__ float g_xs[NSEG * DIM];                          // segment sums (2 MB)
__device__ float g_xm[NSEG * DIM];                          // xs @ Lambda^T (2 MB)
__device__ __align__(16) __nv_bfloat16 g_Gb[DIM * DIM];     // Gamma bf16 [n][k]

__device__ __forceinline__ uint32_t smem_u32(const void* p) {
    uint32_t a;
    asm("{ .reg .u64 t; cvta.to.shared.u64 t, %1; cvt.u32.u64 %0, t; }" : "=r"(a) : "l"(p));
    return a;
}
__device__ __forceinline__ uint32_t pack_bf16x2(float lo, float hi) {
    uint32_t r;
    asm("cvt.rn.bf16x2.f32 %0, %1, %2;" : "=r"(r) : "f"(hi), "f"(lo));
    return r;
}

// ---------------------------------------------------------------------------
// Kernel 0: zero g_xs, convert Gamma_W -> bf16 (plain [n][k] layout)
// ---------------------------------------------------------------------------
__global__ void k0_init(const float* __restrict__ GW) {
    int idx = blockIdx.x * blockDim.x + threadIdx.x;
    if (idx < NSEG * DIM) g_xs[idx] = 0.0f;
    if (idx < DIM * DIM)  g_Gb[idx] = __float2bfloat16(GW[idx]);
}

// ---------------------------------------------------------------------------
// Kernel 1: segment sum (sorted ids, register run-length, boundary atomics)
// ---------------------------------------------------------------------------
__global__ __launch_bounds__(256) void k1_segsum(const float* __restrict__ x,
                                                 const int* __restrict__ seg) {
    int t = threadIdx.x;
    int stream = t >> 5;
    int c = (t & 31) * 4;
    int base = blockIdx.x * 1024 + stream;

    float4 acc = make_float4(0.f, 0.f, 0.f, 0.f);
    int cur = seg[base];

    #pragma unroll 8
    for (int i = 0; i < 128; i++) {
        int r = base + i * 8;
        int s = seg[r];
        float4 v = *(const float4*)(x + (size_t)r * DIM + c);
        if (s != cur) {
            float* d = g_xs + (size_t)cur * DIM + c;
            atomicAdd(d + 0, acc.x); atomicAdd(d + 1, acc.y);
            atomicAdd(d + 2, acc.z); atomicAdd(d + 3, acc.w);
            acc = make_float4(0.f, 0.f, 0.f, 0.f);
            cur = s;
        }
        acc.x += v.x; acc.y += v.y; acc.z += v.z; acc.w += v.w;
    }
    float* d = g_xs + (size_t)cur * DIM + c;
    atomicAdd(d + 0, acc.x); atomicAdd(d + 1, acc.y);
    atomicAdd(d + 2, acc.z); atomicAdd(d + 3, acc.w);
}

// ---------------------------------------------------------------------------
// Kernel 2: g_xm = g_xs @ Lambda_W^T (fp32 exact)
// ---------------------------------------------------------------------------
__global__ __launch_bounds__(128) void k2_xm(const float* __restrict__ LW) {
    extern __shared__ float sm2[];
    float* Lt  = sm2;                 // [128][129]
    float* xss = sm2 + 128 * 129;     // [16][128]
    int t = threadIdx.x;
    int R0 = blockIdx.x * 16;

    for (int i = 0; i < 128; i++) {
        int e = i * 128 + t;
        int j = e >> 7, k = e & 127;
        Lt[k * 129 + j] = LW[e];
    }
    for (int i = 0; i < 16; i++) {
        int e = i * 128 + t;
        int r = e >> 7, k = e & 127;
        xss[r * 128 + k] = g_xs[(size_t)(R0 + r) * DIM + k];
    }
    __syncthreads();

    float acc[16];
    #pragma unroll
    for (int r = 0; r < 16; r++) acc[r] = 0.f;
    for (int k = 0; k < 128; k++) {
        float lv = Lt[k * 129 + t];
        #pragma unroll
        for (int r = 0; r < 16; r++) acc[r] += xss[r * 128 + k] * lv;
    }
    #pragma unroll
    for (int r = 0; r < 16; r++)
        g_xm[(size_t)(R0 + r) * DIM + t] = acc[r];
}

// ---------------------------------------------------------------------------
// Kernel 3: out = x @ Gamma^T (bf16 HMMA) + bias - xm[seg]
// 256 threads = 8 warps; block tile 128x128; warp tile 32x64
// (m-group = warp&3, n-half = warp>>2). LDSM/block = (32+64)*128*2*8 = 192 KB.
// acc = 64 regs/lane -> ~115 total -> 2 CTAs/SM = 16 warps/SM.
// ---------------------------------------------------------------------------
#define ASTRIDE 136
#define K3_SMEM (2 * 128 * ASTRIDE * 2)   // 69632 bytes

__global__ __launch_bounds__(256, 2) void k3_main(const float* __restrict__ x,
                                                  const int* __restrict__ seg,
                                                  const float* __restrict__ bias,
                                                  float* __restrict__ out) {
    extern __shared__ __nv_bfloat16 sm3[];
    __nv_bfloat16* As = sm3;                       // [128][136]
    __nv_bfloat16* Bs = sm3 + 128 * ASTRIDE;       // [128][136]  Bs[n][k]

    int tid  = threadIdx.x;
    int warp = tid >> 5;
    int lane = tid & 31;
    int r0 = blockIdx.x * 128;
    int m0 = (warp & 3) * 32;
    int n0 = (warp >> 2) * 64;
    uint32_t sbB = smem_u32(Bs);
    uint32_t sbA = smem_u32(As);

    // Stage B via cp.async (32 KB, padded rows; bypasses RF)
    #pragma unroll
    for (int i = 0; i < 8; i++) {
        int e = i * 256 + tid;
        int row = e >> 4, c = e & 15;
        asm volatile("cp.async.cg.shared.global [%0], [%1], 16;"
                     :: "r"(sbB + (row * ASTRIDE + c * 8) * 2),
                        "l"((const char*)(g_Gb + row * 128 + c * 8)) : "memory");
    }
    asm volatile("cp.async.commit_group;" ::: "memory");

    // Stage A: LDG fp32 -> bf16 -> STS.128
    #pragma unroll
    for (int i = 0; i < 8; i++) {
        int e = i * 256 + tid;
        int row = e >> 4, g2 = e & 15;
        const float4* src = (const float4*)(x + (size_t)(r0 + row) * DIM + g2 * 8);
        float4 v0 = src[0], v1 = src[1];
        uint32_t p0 = pack_bf16x2(v0.x, v0.y);
        uint32_t p1 = pack_bf16x2(v0.z, v0.w);
        uint32_t p2 = pack_bf16x2(v1.x, v1.y);
        uint32_t p3 = pack_bf16x2(v1.z, v1.w);
        asm volatile("st.shared.v4.b32 [%0], {%1,%2,%3,%4};"
                     :: "r"(sbA + (row * ASTRIDE + g2 * 8) * 2),
                        "r"(p0), "r"(p1), "r"(p2), "r"(p3) : "memory");
    }

    // Prefetch epilogue seg ids (4 rows/lane)
    int g  = lane >> 2;
    int t4 = lane & 3;
    int sa[2], sb2[2];
    #pragma unroll
    for (int mt = 0; mt < 2; mt++) {
        int ra = r0 + m0 + mt * 16 + g;
        sa[mt]  = seg[ra];
        sb2[mt] = seg[ra + 8];
    }

    asm volatile("cp.async.wait_group 0;" ::: "memory");
    __syncthreads();

    // Fragment base addresses
    const __nv_bfloat16* ap[2];
    #pragma unroll
    for (int mt = 0; mt < 2; mt++)
        ap[mt] = As + (m0 + mt * 16 + (lane & 15)) * ASTRIDE + ((lane >> 4) << 3);
    const __nv_bfloat16* bp =
        Bs + (n0 + (lane & 7) + ((lane >> 4) << 3)) * ASTRIDE + (((lane >> 3) & 1) << 3);

    float acc[2][8][4];
    #pragma unroll
    for (int mt = 0; mt < 2; mt++)
        #pragma unroll
        for (int nt = 0; nt < 8; nt++)
            #pragma unroll
            for (int q = 0; q < 4; q++) acc[mt][nt][q] = 0.f;

    #pragma unroll
    for (int ks = 0; ks < 8; ks++) {
        uint32_t a[2][4], b[4][4];
        #pragma unroll
        for (int mt = 0; mt < 2; mt++) {
            uint32_t addr = (uint32_t)__cvta_generic_to_shared(ap[mt] + ks * 16);
            asm volatile(
                "ldmatrix.sync.aligned.m8n8.x4.shared.b16 {%0,%1,%2,%3}, [%4];"
                : "=r"(a[mt][0]), "=r"(a[mt][1]), "=r"(a[mt][2]), "=r"(a[mt][3])
                : "r"(addr));
        }
        #pragma unroll
        for (int np = 0; np < 4; np++) {
            uint32_t addr = (uint32_t)__cvta_generic_to_shared(
                bp + np * 16 * ASTRIDE + ks * 16);
            asm volatile(
                "ldmatrix.sync.aligned.m8n8.x4.shared.b16 {%0,%1,%2,%3}, [%4];"
                : "=r"(b[np][0]), "=r"(b[np][1]), "=r"(b[np][2]), "=r"(b[np][3])
                : "r"(addr));
        }
        #pragma unroll
        for (int mt = 0; mt < 2; mt++)
            #pragma unroll
            for (int np = 0; np < 4; np++) {
                asm volatile(
                    "mma.sync.aligned.m16n8k16.row.col.f32.bf16.bf16.f32 "
                    "{%0,%1,%2,%3}, {%4,%5,%6,%7}, {%8,%9}, {%0,%1,%2,%3};\n"
                    : "+f"(acc[mt][2 * np][0]), "+f"(acc[mt][2 * np][1]),
                      "+f"(acc[mt][2 * np][2]), "+f"(acc[mt][2 * np][3])
                    : "r"(a[mt][0]), "r"(a[mt][1]), "r"(a[mt][2]), "r"(a[mt][3]),
                      "r"(b[np][0]), "r"(b[np][1]));
                asm volatile(
                    "mma.sync.aligned.m16n8k16.row.col.f32.bf16.bf16.f32 "
                    "{%0,%1,%2,%3}, {%4,%5,%6,%7}, {%8,%9}, {%0,%1,%2,%3};\n"
                    : "+f"(acc[mt][2 * np + 1][0]), "+f"(acc[mt][2 * np + 1][1]),
                      "+f"(acc[mt][2 * np + 1][2]), "+f"(acc[mt][2 * np + 1][3])
                    : "r"(a[mt][0]), "r"(a[mt][1]), "r"(a[mt][2]), "r"(a[mt][3]),
                      "r"(b[np][2]), "r"(b[np][3]));
            }
    }

    // Epilogue: + bias - xm[seg]; sector-aligned float2 stores
    float2 bias_r[8];
    #pragma unroll
    for (int nt = 0; nt < 8; nt++)
        bias_r[nt] = *(const float2*)(bias + n0 + nt * 8 + 2 * t4);

    #pragma unroll
    for (int mt = 0; mt < 2; mt++) {
        const float* xa = g_xm + (size_t)sa[mt] * DIM;
        const float* xb = g_xm + (size_t)sb2[mt] * DIM;
        int ra = r0 + m0 + mt * 16 + g;
        int rb = ra + 8;
        #pragma unroll
        for (int nt = 0; nt < 8; nt++) {
            int j = n0 + nt * 8 + 2 * t4;
            float2 ma = *(const float2*)(xa + j);
            float2 mb = *(const float2*)(xb + j);
            float2 oa, ob;
            oa.x = acc[mt][nt][0] + bias_r[nt].x - ma.x;
            oa.y = acc[mt][nt][1] + bias_r[nt].y - ma.y;
            ob.x = acc[mt][nt][2] + bias_r[nt].x - mb.x;
            ob.y = acc[mt][nt][3] + bias_r[nt].y - mb.y;
            *(float2*)(out + (size_t)ra * DIM + j) = oa;
            *(float2*)(out + (size_t)rb * DIM + j) = ob;
        }
    }
}

// ---------------------------------------------------------------------------
extern "C" void kernel_launch(void* const* d_in, const int* in_sizes, int n_in,
                              void* d_out, int out_size) {
    const float* x   = (const float*)d_in[0];
    const int*   seg = (const int*)d_in[1];
    const float* GW = nullptr;
    const float* Gb = nullptr;
    const float* LW = nullptr;
    for (int i = 2; i < n_in; i++) {
        int s = in_sizes[i];
        if (s == DIM * DIM) { if (!GW) GW = (const float*)d_in[i]; else LW = (const float*)d_in[i]; }
        else if (s == DIM) { Gb = (const float*)d_in[i]; }
    }
    float* out = (float*)d_out;

    cudaFuncSetAttribute(k2_xm,   cudaFuncAttributeMaxDynamicSharedMemorySize, 74240);
    cudaFuncSetAttribute(k3_main, cudaFuncAttributeMaxDynamicSharedMemorySize, K3_SMEM);

    k0_init<<<2048, 256>>>(GW);
    k1_segsum<<<NROWS / 1024, 256>>>(x, seg);
    k2_xm<<<NSEG / 16, 128, 74240>>>(LW);
    k3_main<<<NROWS / 128, 256, K3_SMEM>>>(x, seg, Gb, out);
}